// round 2
// baseline (speedup 1.0000x reference)
#include <cuda_runtime.h>
#include <math.h>

#define NN 20000
#define EE 320000
#define ET 340000   // EE + NN self loops
#define BG 32
#define FH 256      // H*C
#define HH 4
#define CC 64

// ---------------- scratch (device globals; no allocation allowed) ----------
__device__ float g_X0[NN * 64];
__device__ float g_buf1[NN * FH];   // GEMM output (h)
__device__ float g_buf2[NN * FH];   // aggregation output
__device__ float g_as[NN * HH];
__device__ float g_ad[NN * HH];
__device__ int   g_deg[NN];
__device__ int   g_rowptr[NN + 1];
__device__ int   g_cursor[NN];
__device__ int   g_col[ET];
__device__ float g_pool[BG * FH];
__device__ int   g_cnt[BG];

// ---------------- concat(pos, x) -> X0 [N,64] ------------------------------
__global__ void concat_kernel(const float* __restrict__ x, const float* __restrict__ pos) {
    int idx = blockIdx.x * blockDim.x + threadIdx.x;
    if (idx >= NN * 64) return;
    int n = idx >> 6, c = idx & 63;
    g_X0[idx] = (c < 2) ? pos[n * 2 + c] : x[n * 62 + (c - 2)];
}

// ---------------- CSR build -------------------------------------------------
__global__ void init_deg_kernel() {
    int n = blockIdx.x * blockDim.x + threadIdx.x;
    if (n < NN) g_deg[n] = 1;   // self loop
}

__global__ void hist_kernel(const int* __restrict__ ei) {
    int e = blockIdx.x * blockDim.x + threadIdx.x;
    if (e >= EE) return;
    int dst = ei[EE + e];
    atomicAdd(&g_deg[dst], 1);
}

// exclusive scan over g_deg (N=20000) with a single 1024-thread block
__global__ void scan_kernel() {
    __shared__ int s[1024];
    int tid = threadIdx.x;
    const int CH = 20;                 // 1024*20 = 20480 >= 20000
    int base = tid * CH;
    int sum = 0;
    #pragma unroll
    for (int i = 0; i < CH; i++) {
        int idx = base + i;
        sum += (idx < NN) ? g_deg[idx] : 0;
    }
    s[tid] = sum;
    __syncthreads();
    // Hillis-Steele inclusive scan
    for (int off = 1; off < 1024; off <<= 1) {
        int v = (tid >= off) ? s[tid - off] : 0;
        __syncthreads();
        s[tid] += v;
        __syncthreads();
    }
    int prefix = (tid == 0) ? 0 : s[tid - 1];
    int run = prefix;
    #pragma unroll
    for (int i = 0; i < CH; i++) {
        int idx = base + i;
        if (idx < NN) { g_rowptr[idx] = run; run += g_deg[idx]; }
    }
    if (tid == 0) g_rowptr[NN] = s[1023];
}

__global__ void selfloop_kernel() {
    int n = blockIdx.x * blockDim.x + threadIdx.x;
    if (n >= NN) return;
    int p = g_rowptr[n];
    g_col[p] = n;            // self loop first
    g_cursor[n] = p + 1;
}

__global__ void scatter_kernel(const int* __restrict__ ei) {
    int e = blockIdx.x * blockDim.x + threadIdx.x;
    if (e >= EE) return;
    int src = ei[e];
    int dst = ei[EE + e];
    int p = atomicAdd(&g_cursor[dst], 1);
    g_col[p] = src;
}

// ---------------- SGEMM: C[M,Nn] = A[M,K] @ B[K,Nn] ------------------------
// BM=64 BN=64 BK=16, 256 threads, 4x4 per thread
__global__ void sgemm_kernel(const float* __restrict__ A, const float* __restrict__ Bw,
                             float* __restrict__ C, int M, int K, int Nn) {
    __shared__ float As[16][65];
    __shared__ float Bs[16][64];
    int tid = threadIdx.x;
    int bm = blockIdx.x * 64, bn = blockIdx.y * 64;
    int ty = tid >> 4, tx = tid & 15;
    int ar = tid >> 2, ac = (tid & 3) * 4;    // A tile load: row 0..63, k 0..15
    int br = tid >> 4, bc = (tid & 15) * 4;   // B tile load: k 0..15, col 0..63

    float acc[4][4];
    #pragma unroll
    for (int i = 0; i < 4; i++)
        #pragma unroll
        for (int j = 0; j < 4; j++) acc[i][j] = 0.f;

    for (int k0 = 0; k0 < K; k0 += 16) {
        int grow = bm + ar;
        float4 av = make_float4(0.f, 0.f, 0.f, 0.f);
        if (grow < M) av = *(const float4*)(A + (size_t)grow * K + k0 + ac);
        As[ac + 0][ar] = av.x; As[ac + 1][ar] = av.y;
        As[ac + 2][ar] = av.z; As[ac + 3][ar] = av.w;
        float4 bv = *(const float4*)(Bw + (size_t)(k0 + br) * Nn + bn + bc);
        *(float4*)&Bs[br][bc] = bv;
        __syncthreads();
        #pragma unroll
        for (int kk = 0; kk < 16; kk++) {
            float a4[4];
            #pragma unroll
            for (int i = 0; i < 4; i++) a4[i] = As[kk][ty * 4 + i];
            float4 b4 = *(float4*)&Bs[kk][tx * 4];
            float bb[4] = {b4.x, b4.y, b4.z, b4.w};
            #pragma unroll
            for (int i = 0; i < 4; i++)
                #pragma unroll
                for (int j = 0; j < 4; j++)
                    acc[i][j] = fmaf(a4[i], bb[j], acc[i][j]);
        }
        __syncthreads();
    }
    #pragma unroll
    for (int i = 0; i < 4; i++) {
        int row = bm + ty * 4 + i;
        if (row < M) {
            float4 v = make_float4(acc[i][0], acc[i][1], acc[i][2], acc[i][3]);
            *(float4*)(C + (size_t)row * Nn + bn + tx * 4) = v;
        }
    }
}

// ---------------- alpha_s / alpha_d: per (node, head) dot -------------------
__global__ void alpha_kernel(const float* __restrict__ h, const float* __restrict__ a_src,
                             const float* __restrict__ a_dst) {
    __shared__ float s_as[FH], s_ad[FH];
    int tid = threadIdx.x;                 // 128 threads
    s_as[tid] = a_src[tid]; s_as[tid + 128] = a_src[tid + 128];
    s_ad[tid] = a_dst[tid]; s_ad[tid + 128] = a_dst[tid + 128];
    __syncthreads();
    int n = blockIdx.x;
    int hd = tid >> 5, lane = tid & 31;
    const float* hr = h + (size_t)n * FH + hd * CC;
    float v0 = hr[lane], v1 = hr[lane + 32];
    float ds = v0 * s_as[hd * CC + lane] + v1 * s_as[hd * CC + lane + 32];
    float dd = v0 * s_ad[hd * CC + lane] + v1 * s_ad[hd * CC + lane + 32];
    #pragma unroll
    for (int off = 16; off > 0; off >>= 1) {
        ds += __shfl_down_sync(0xffffffff, ds, off);
        dd += __shfl_down_sync(0xffffffff, dd, off);
    }
    if (lane == 0) { g_as[n * HH + hd] = ds; g_ad[n * HH + hd] = dd; }
}

// ---------------- attention aggregation: one block per dst node -------------
__global__ void aggregate_kernel(const float* __restrict__ h, const float* __restrict__ bias,
                                 float* __restrict__ outp) {
    int n = blockIdx.x;
    int tid = threadIdx.x;                  // 128
    int start = g_rowptr[n], end = g_rowptr[n + 1];

    __shared__ float s_red[HH][128];
    __shared__ float s_m[HH];
    __shared__ float s_rd[HH];
    __shared__ float s_alpha[32][HH];
    __shared__ int   s_src[32];

    float adh[HH];
    #pragma unroll
    for (int hd = 0; hd < HH; hd++) adh[hd] = g_ad[n * HH + hd];

    // pass 1: max
    float m[HH] = {-1e30f, -1e30f, -1e30f, -1e30f};
    for (int j = start + tid; j < end; j += 128) {
        int s = g_col[j];
        #pragma unroll
        for (int hd = 0; hd < HH; hd++) {
            float e = g_as[s * HH + hd] + adh[hd];
            e = (e > 0.f) ? e : 0.2f * e;
            m[hd] = fmaxf(m[hd], e);
        }
    }
    #pragma unroll
    for (int hd = 0; hd < HH; hd++) s_red[hd][tid] = m[hd];
    __syncthreads();
    for (int off = 64; off > 0; off >>= 1) {
        if (tid < off)
            #pragma unroll
            for (int hd = 0; hd < HH; hd++)
                s_red[hd][tid] = fmaxf(s_red[hd][tid], s_red[hd][tid + off]);
        __syncthreads();
    }
    if (tid < HH) s_m[tid] = s_red[tid][0];
    __syncthreads();

    // pass 2: denom
    float d[HH] = {0.f, 0.f, 0.f, 0.f};
    for (int j = start + tid; j < end; j += 128) {
        int s = g_col[j];
        #pragma unroll
        for (int hd = 0; hd < HH; hd++) {
            float e = g_as[s * HH + hd] + adh[hd];
            e = (e > 0.f) ? e : 0.2f * e;
            d[hd] += __expf(e - s_m[hd]);
        }
    }
    #pragma unroll
    for (int hd = 0; hd < HH; hd++) s_red[hd][tid] = d[hd];
    __syncthreads();
    for (int off = 64; off > 0; off >>= 1) {
        if (tid < off)
            #pragma unroll
            for (int hd = 0; hd < HH; hd++)
                s_red[hd][tid] += s_red[hd][tid + off];
        __syncthreads();
    }
    if (tid < HH) s_rd[tid] = 1.f / (s_red[tid][0] + 1e-16f);
    __syncthreads();

    // pass 3: weighted gather-accumulate, 2 channels / thread
    float acc0 = 0.f, acc1 = 0.f;
    int c0 = 2 * tid;
    int myh = tid >> 5;         // head of channels 2*tid, 2*tid+1
    for (int base = start; base < end; base += 32) {
        int cnt = min(32, end - base);
        if (tid < cnt) {
            int s = g_col[base + tid];
            s_src[tid] = s;
            #pragma unroll
            for (int hd = 0; hd < HH; hd++) {
                float e = g_as[s * HH + hd] + adh[hd];
                e = (e > 0.f) ? e : 0.2f * e;
                s_alpha[tid][hd] = __expf(e - s_m[hd]) * s_rd[hd];
            }
        }
        __syncthreads();
        for (int k = 0; k < cnt; k++) {
            int s = s_src[k];
            float a = s_alpha[k][myh];
            float2 hv = *(const float2*)(h + (size_t)s * FH + c0);
            acc0 = fmaf(hv.x, a, acc0);
            acc1 = fmaf(hv.y, a, acc1);
        }
        __syncthreads();
    }
    outp[(size_t)n * FH + c0]     = acc0 + bias[c0];
    outp[(size_t)n * FH + c0 + 1] = acc1 + bias[c0 + 1];
}

// ---------------- pooling ---------------------------------------------------
__global__ void zero_pool_kernel() {
    int i = blockIdx.x * blockDim.x + threadIdx.x;
    if (i < BG * FH) g_pool[i] = 0.f;
    if (i < BG) g_cnt[i] = 0;
}

__global__ void count_kernel(const int* __restrict__ batch) {
    __shared__ int s[256];
    int b = blockIdx.x, tid = threadIdx.x;
    int c = 0;
    for (int i = tid; i < NN; i += 256) c += (batch[i] == b);
    s[tid] = c;
    __syncthreads();
    for (int off = 128; off > 0; off >>= 1) {
        if (tid < off) s[tid] += s[tid + off];
        __syncthreads();
    }
    if (tid == 0) g_cnt[b] = s[0];
}

__global__ void pool_kernel(const float* __restrict__ outp, const int* __restrict__ batch) {
    int n0 = blockIdx.x * 64;
    int tid = threadIdx.x;                // 256 = channel
    int nend = min(n0 + 64, NN);
    float acc = 0.f;
    int cur = batch[n0];
    for (int n = n0; n < nend; n++) {
        int bb = batch[n];
        if (bb != cur) {
            atomicAdd(&g_pool[cur * FH + tid], acc);
            acc = 0.f; cur = bb;
        }
        acc += outp[(size_t)n * FH + tid];
    }
    atomicAdd(&g_pool[cur * FH + tid], acc);
}

// ---------------- MLP tail ---------------------------------------------------
__global__ void mlp_kernel(const float* __restrict__ lw1, const float* __restrict__ lb1,
                           const float* __restrict__ lw2, const float* __restrict__ lb2,
                           float* __restrict__ out) {
    __shared__ float s_in[FH];
    __shared__ float s_mid[128];
    int g = blockIdx.x, tid = threadIdx.x;   // 128 threads
    float inv = 1.f / fmaxf((float)g_cnt[g], 1.f);
    s_in[tid]       = g_pool[g * FH + tid] * inv;
    s_in[tid + 128] = g_pool[g * FH + tid + 128] * inv;
    __syncthreads();
    float acc = lb1[tid];
    #pragma unroll 8
    for (int k = 0; k < FH; k++) acc = fmaf(s_in[k], lw1[k * 128 + tid], acc);
    s_mid[tid] = fmaxf(acc, 0.f);
    __syncthreads();
    if (tid < 10) {
        float a = lb2[tid];
        #pragma unroll 8
        for (int k = 0; k < 128; k++) a = fmaf(s_mid[k], lw2[k * 10 + tid], a);
        out[g * 10 + tid] = fmaxf(a, 0.f);
    }
}

// ---------------- launch ------------------------------------------------------
extern "C" void kernel_launch(void* const* d_in, const int* in_sizes, int n_in,
                              void* d_out, int out_size) {
    const float* x     = (const float*)d_in[0];
    const float* pos   = (const float*)d_in[1];
    const int*   ei    = (const int*)d_in[2];
    const int*   batch = (const int*)d_in[3];
    const float* W1   = (const float*)d_in[4];
    const float* as1  = (const float*)d_in[5];
    const float* ad1  = (const float*)d_in[6];
    const float* b1   = (const float*)d_in[7];
    const float* W2   = (const float*)d_in[8];
    const float* as2  = (const float*)d_in[9];
    const float* ad2  = (const float*)d_in[10];
    const float* b2   = (const float*)d_in[11];
    const float* lw1  = (const float*)d_in[12];
    const float* lb1  = (const float*)d_in[13];
    const float* lw2  = (const float*)d_in[14];
    const float* lb2  = (const float*)d_in[15];
    float* out = (float*)d_out;

    float *p_X0, *p_b1, *p_b2;
    cudaGetSymbolAddress((void**)&p_X0, g_X0);
    cudaGetSymbolAddress((void**)&p_b1, g_buf1);
    cudaGetSymbolAddress((void**)&p_b2, g_buf2);

    concat_kernel<<<(NN * 64 + 255) / 256, 256>>>(x, pos);

    // CSR build (by destination), self loops first
    init_deg_kernel<<<(NN + 255) / 256, 256>>>();
    hist_kernel<<<(EE + 255) / 256, 256>>>(ei);
    scan_kernel<<<1, 1024>>>();
    selfloop_kernel<<<(NN + 255) / 256, 256>>>();
    scatter_kernel<<<(EE + 255) / 256, 256>>>(ei);

    dim3 g1((NN + 63) / 64, 4);

    // ---- GAT layer 1 ----
    sgemm_kernel<<<g1, 256>>>(p_X0, W1, p_b1, NN, 64, FH);
    alpha_kernel<<<NN, 128>>>(p_b1, as1, ad1);
    aggregate_kernel<<<NN, 128>>>(p_b1, b1, p_b2);

    // ---- GAT layer 2 ----
    sgemm_kernel<<<g1, 256>>>(p_b2, W2, p_b1, NN, FH, FH);
    alpha_kernel<<<NN, 128>>>(p_b1, as2, ad2);
    aggregate_kernel<<<NN, 128>>>(p_b1, b2, p_b2);

    // ---- pool + MLP ----
    zero_pool_kernel<<<(BG * FH + 255) / 256, 256>>>();
    count_kernel<<<BG, 256>>>(batch);
    pool_kernel<<<(NN + 63) / 64, 256>>>(p_b2, batch);
    mlp_kernel<<<BG, 128>>>(lw1, lb1, lw2, lb2, out);
}

// round 3
// speedup vs baseline: 1.1469x; 1.1469x over previous
#include <cuda_runtime.h>
#include <math.h>

#define NN 20000
#define EE 320000
#define ET 340000   // EE + NN self loops
#define BG 32
#define FH 256      // H*C
#define HH 4
#define CC 64

typedef unsigned long long ull;

// ---------------- packed f32x2 helpers (FFMA2 — 2x fp32 FMA throughput) -----
__device__ __forceinline__ void fma2(ull &d, ull a, ull b) {
    asm("fma.rn.f32x2 %0, %1, %2, %0;" : "+l"(d) : "l"(a), "l"(b));
}
__device__ __forceinline__ ull add2(ull a, ull b) {
    ull r; asm("add.rn.f32x2 %0, %1, %2;" : "=l"(r) : "l"(a), "l"(b)); return r;
}
__device__ __forceinline__ ull dup2(float x) {
    ull r; asm("mov.b64 %0, {%1, %1};" : "=l"(r) : "f"(x)); return r;
}
__device__ __forceinline__ void unpack2(ull v, float &lo, float &hi) {
    asm("mov.b64 {%0, %1}, %2;" : "=f"(lo), "=f"(hi) : "l"(v));
}

// ---------------- scratch (device globals; no allocation allowed) ----------
__device__ __align__(16) float g_buf1[NN * FH];   // GEMM output (h)
__device__ __align__(16) float g_buf2[NN * FH];   // aggregation output
__device__ __align__(16) float g_as[NN * HH];
__device__ __align__(16) float g_ad[NN * HH];
__device__ __align__(16) int   g_deg[NN];
__device__ __align__(16) int   g_rowptr[NN + 1];
__device__ int   g_cursor[NN];
__device__ int   g_col[ET];
__device__ float g_pool[BG * FH];
__device__ int   g_cnt[BG];

// ---------------- CSR build -------------------------------------------------
__global__ void init_deg_kernel() {
    int n = blockIdx.x * blockDim.x + threadIdx.x;
    if (n < NN) g_deg[n] = 1;   // self loop
}

__global__ void hist_kernel(const int* __restrict__ ei) {
    int e = blockIdx.x * blockDim.x + threadIdx.x;
    if (e >= EE) return;
    int dst = ei[EE + e];
    atomicAdd(&g_deg[dst], 1);
}

// exclusive scan over g_deg (N=20000): int4 + warp-shuffle, single block
__global__ void scan_kernel() {
    __shared__ int wsum[32];
    int tid = threadIdx.x;
    int lane = tid & 31, wid = tid >> 5;
    int4 v[5];
    int sum = 0;
    if (tid < 1000) {               // 1000 * 20 = 20000 exactly
        const int4* p = (const int4*)(g_deg + tid * 20);
        #pragma unroll
        for (int i = 0; i < 5; i++) {
            v[i] = p[i];
            sum += v[i].x + v[i].y + v[i].z + v[i].w;
        }
    }
    int inc = sum;
    #pragma unroll
    for (int off = 1; off < 32; off <<= 1) {
        int u = __shfl_up_sync(0xffffffffu, inc, off);
        if (lane >= off) inc += u;
    }
    if (lane == 31) wsum[wid] = inc;
    __syncthreads();
    if (wid == 0) {
        int w = wsum[lane];
        #pragma unroll
        for (int off = 1; off < 32; off <<= 1) {
            int u = __shfl_up_sync(0xffffffffu, w, off);
            if (lane >= off) w += u;
        }
        wsum[lane] = w;
    }
    __syncthreads();
    int excl = inc - sum + (wid ? wsum[wid - 1] : 0);
    if (tid < 1000) {
        int run = excl;
        int4* q = (int4*)(g_rowptr + tid * 20);
        #pragma unroll
        for (int i = 0; i < 5; i++) {
            int4 o;
            o.x = run; run += v[i].x;
            o.y = run; run += v[i].y;
            o.z = run; run += v[i].z;
            o.w = run; run += v[i].w;
            q[i] = o;
        }
    }
    if (tid == 0) g_rowptr[NN] = wsum[31];
}

__global__ void selfloop_kernel() {
    int n = blockIdx.x * blockDim.x + threadIdx.x;
    if (n >= NN) return;
    int p = g_rowptr[n];
    g_col[p] = n;            // self loop first
    g_cursor[n] = p + 1;
}

__global__ void scatter_kernel(const int* __restrict__ ei) {
    int e = blockIdx.x * blockDim.x + threadIdx.x;
    if (e >= EE) return;
    int src = ei[e];
    int dst = ei[EE + e];
    int p = atomicAdd(&g_cursor[dst], 1);
    g_col[p] = src;
}

// ---------------- SGEMM (FFMA2) + fused concat(A) + fused alpha dots --------
// C[NN,256] = A[NN,K] @ B[K,256]; BM=128 BN=64(=one head) BK=16, 256 thr,
// micro 8(M)x4(N) per thread, M-pairs packed in f32x2.
__global__ void __launch_bounds__(256, 2)
sgemm_fused(const float* __restrict__ A, const float* __restrict__ x,
            const float* __restrict__ pos, const float* __restrict__ Bw,
            float* __restrict__ C, int K, int mode,
            const float* __restrict__ a_src, const float* __restrict__ a_dst) {
    __shared__ float As[16][132];   // [k][m], padded
    __shared__ float Bs[16][64];    // [k][n]
    __shared__ float s_as[64], s_ad[64];

    int tid = threadIdx.x;
    int bm = blockIdx.x * 128;
    int hd = blockIdx.y;            // head index (BN == CC)
    int bn = hd * 64;

    if (tid < 64) { s_as[tid] = a_src[bn + tid]; s_ad[tid] = a_dst[bn + tid]; }

    int ty = tid >> 4, tx = tid & 15;
    int m0 = ty * 8, n0 = tx * 4;
    int ar = tid >> 2;              // 0..63
    int ac = (tid & 3) * 4;         // 0,4,8,12
    int br = tid >> 4;              // 0..15
    int bc = (tid & 15) * 4;        // 0..60

    ull acc[4][4];
    #pragma unroll
    for (int i = 0; i < 4; i++)
        #pragma unroll
        for (int j = 0; j < 4; j++) acc[i][j] = 0ull;

    for (int k0 = 0; k0 < K; k0 += 16) {
        #pragma unroll
        for (int half = 0; half < 2; half++) {
            int r = ar + half * 64;
            int row = bm + r;
            float4 v = make_float4(0.f, 0.f, 0.f, 0.f);
            if (row < NN) {
                if (mode == 0) {
                    v = *(const float4*)(A + (size_t)row * K + k0 + ac);
                } else {
                    int c = k0 + ac;      // concat(pos[2], x[62])
                    if (c == 0) {
                        float2 p = *(const float2*)(pos + (size_t)row * 2);
                        float2 q = *(const float2*)(x + (size_t)row * 62);
                        v = make_float4(p.x, p.y, q.x, q.y);
                    } else {
                        float2 q0 = *(const float2*)(x + (size_t)row * 62 + c - 2);
                        float2 q1 = *(const float2*)(x + (size_t)row * 62 + c);
                        v = make_float4(q0.x, q0.y, q1.x, q1.y);
                    }
                }
            }
            As[ac + 0][r] = v.x; As[ac + 1][r] = v.y;
            As[ac + 2][r] = v.z; As[ac + 3][r] = v.w;
        }
        *(float4*)&Bs[br][bc] = *(const float4*)(Bw + (size_t)(k0 + br) * FH + bn + bc);
        __syncthreads();
        #pragma unroll
        for (int kk = 0; kk < 16; kk++) {
            float4 b4 = *(float4*)&Bs[kk][n0];
            ull bb0 = dup2(b4.x), bb1 = dup2(b4.y), bb2 = dup2(b4.z), bb3 = dup2(b4.w);
            ulonglong2 a01 = *(ulonglong2*)&As[kk][m0];
            ulonglong2 a23 = *(ulonglong2*)&As[kk][m0 + 4];
            ull aa[4] = {a01.x, a01.y, a23.x, a23.y};
            #pragma unroll
            for (int mi = 0; mi < 4; mi++) {
                fma2(acc[mi][0], aa[mi], bb0);
                fma2(acc[mi][1], aa[mi], bb1);
                fma2(acc[mi][2], aa[mi], bb2);
                fma2(acc[mi][3], aa[mi], bb3);
            }
        }
        __syncthreads();
    }

    // ---- fused alpha dots: partial = sum_n h[m][n]*a[n], reduce over tx ----
    ull ps[4] = {0,0,0,0}, pd[4] = {0,0,0,0};
    #pragma unroll
    for (int nj = 0; nj < 4; nj++) {
        ull w_s = dup2(s_as[n0 + nj]);
        ull w_d = dup2(s_ad[n0 + nj]);
        #pragma unroll
        for (int mi = 0; mi < 4; mi++) {
            fma2(ps[mi], acc[mi][nj], w_s);
            fma2(pd[mi], acc[mi][nj], w_d);
        }
    }
    #pragma unroll
    for (int s = 1; s < 16; s <<= 1) {
        #pragma unroll
        for (int mi = 0; mi < 4; mi++) {
            ps[mi] = add2(ps[mi], __shfl_xor_sync(0xffffffffu, ps[mi], s));
            pd[mi] = add2(pd[mi], __shfl_xor_sync(0xffffffffu, pd[mi], s));
        }
    }
    if (tx == 0) {
        #pragma unroll
        for (int mi = 0; mi < 4; mi++) {
            int row = bm + m0 + 2 * mi;
            float slo, shi, dlo, dhi;
            unpack2(ps[mi], slo, shi);
            unpack2(pd[mi], dlo, dhi);
            if (row < NN)     { g_as[row * HH + hd] = slo; g_ad[row * HH + hd] = dlo; }
            if (row + 1 < NN) { g_as[(row + 1) * HH + hd] = shi; g_ad[(row + 1) * HH + hd] = dhi; }
        }
    }

    // ---- C writes ----
    #pragma unroll
    for (int mi = 0; mi < 4; mi++) {
        int row = bm + m0 + 2 * mi;
        float lo0, hi0, lo1, hi1, lo2, hi2, lo3, hi3;
        unpack2(acc[mi][0], lo0, hi0);
        unpack2(acc[mi][1], lo1, hi1);
        unpack2(acc[mi][2], lo2, hi2);
        unpack2(acc[mi][3], lo3, hi3);
        if (row < NN)
            *(float4*)(C + (size_t)row * FH + bn + n0) = make_float4(lo0, lo1, lo2, lo3);
        if (row + 1 < NN)
            *(float4*)(C + (size_t)(row + 1) * FH + bn + n0) = make_float4(hi0, hi1, hi2, hi3);
    }
}

// ---------------- attention aggregation: one block per dst node -------------
__global__ void aggregate_kernel(const float* __restrict__ h, const float* __restrict__ bias,
                                 float* __restrict__ outp) {
    int n = blockIdx.x;
    int tid = threadIdx.x;                  // 128
    int start = g_rowptr[n], end = g_rowptr[n + 1];

    __shared__ float s_red[HH][128];
    __shared__ float s_m[HH];
    __shared__ float s_rd[HH];
    __shared__ float s_alpha[32][HH];
    __shared__ int   s_src[32];

    const float4* as4 = (const float4*)g_as;
    float4 adv = ((const float4*)g_ad)[n];
    float adh[HH] = {adv.x, adv.y, adv.z, adv.w};

    // pass 1: max
    float m[HH] = {-1e30f, -1e30f, -1e30f, -1e30f};
    for (int j = start + tid; j < end; j += 128) {
        int s = g_col[j];
        float4 av = as4[s];
        float ee[HH] = {av.x + adh[0], av.y + adh[1], av.z + adh[2], av.w + adh[3]};
        #pragma unroll
        for (int hd = 0; hd < HH; hd++) {
            float e = ee[hd];
            e = (e > 0.f) ? e : 0.2f * e;
            m[hd] = fmaxf(m[hd], e);
        }
    }
    #pragma unroll
    for (int hd = 0; hd < HH; hd++) s_red[hd][tid] = m[hd];
    __syncthreads();
    for (int off = 64; off > 0; off >>= 1) {
        if (tid < off)
            #pragma unroll
            for (int hd = 0; hd < HH; hd++)
                s_red[hd][tid] = fmaxf(s_red[hd][tid], s_red[hd][tid + off]);
        __syncthreads();
    }
    if (tid < HH) s_m[tid] = s_red[tid][0];
    __syncthreads();

    // pass 2: denom
    float d[HH] = {0.f, 0.f, 0.f, 0.f};
    for (int j = start + tid; j < end; j += 128) {
        int s = g_col[j];
        float4 av = as4[s];
        float ee[HH] = {av.x + adh[0], av.y + adh[1], av.z + adh[2], av.w + adh[3]};
        #pragma unroll
        for (int hd = 0; hd < HH; hd++) {
            float e = ee[hd];
            e = (e > 0.f) ? e : 0.2f * e;
            d[hd] += __expf(e - s_m[hd]);
        }
    }
    #pragma unroll
    for (int hd = 0; hd < HH; hd++) s_red[hd][tid] = d[hd];
    __syncthreads();
    for (int off = 64; off > 0; off >>= 1) {
        if (tid < off)
            #pragma unroll
            for (int hd = 0; hd < HH; hd++)
                s_red[hd][tid] += s_red[hd][tid + off];
        __syncthreads();
    }
    if (tid < HH) s_rd[tid] = 1.f / (s_red[tid][0] + 1e-16f);
    __syncthreads();

    // pass 3: weighted gather-accumulate, 2 channels / thread
    float acc0 = 0.f, acc1 = 0.f;
    int c0 = 2 * tid;
    int myh = tid >> 5;         // head of channels 2*tid, 2*tid+1
    for (int base = start; base < end; base += 32) {
        int cnt = min(32, end - base);
        if (tid < cnt) {
            int s = g_col[base + tid];
            s_src[tid] = s;
            float4 av = as4[s];
            float ee[HH] = {av.x + adh[0], av.y + adh[1], av.z + adh[2], av.w + adh[3]};
            #pragma unroll
            for (int hd = 0; hd < HH; hd++) {
                float e = ee[hd];
                e = (e > 0.f) ? e : 0.2f * e;
                s_alpha[tid][hd] = __expf(e - s_m[hd]) * s_rd[hd];
            }
        }
        __syncthreads();
        for (int k = 0; k < cnt; k++) {
            int s = s_src[k];
            float a = s_alpha[k][myh];
            float2 hv = *(const float2*)(h + (size_t)s * FH + c0);
            acc0 = fmaf(hv.x, a, acc0);
            acc1 = fmaf(hv.y, a, acc1);
        }
        __syncthreads();
    }
    outp[(size_t)n * FH + c0]     = acc0 + bias[c0];
    outp[(size_t)n * FH + c0 + 1] = acc1 + bias[c0 + 1];
}

// ---------------- pooling ---------------------------------------------------
__global__ void zero_pool_kernel() {
    int i = blockIdx.x * blockDim.x + threadIdx.x;
    if (i < BG * FH) g_pool[i] = 0.f;
    if (i < BG) g_cnt[i] = 0;
}

__global__ void count_kernel(const int* __restrict__ batch) {
    __shared__ int s[256];
    int b = blockIdx.x, tid = threadIdx.x;
    int c = 0;
    for (int i = tid; i < NN; i += 256) c += (batch[i] == b);
    s[tid] = c;
    __syncthreads();
    for (int off = 128; off > 0; off >>= 1) {
        if (tid < off) s[tid] += s[tid + off];
        __syncthreads();
    }
    if (tid == 0) g_cnt[b] = s[0];
}

__global__ void pool_kernel(const float* __restrict__ outp, const int* __restrict__ batch) {
    int n0 = blockIdx.x * 64;
    int tid = threadIdx.x;                // 256 = channel
    int nend = min(n0 + 64, NN);
    float acc = 0.f;
    int cur = batch[n0];
    for (int n = n0; n < nend; n++) {
        int bb = batch[n];
        if (bb != cur) {
            atomicAdd(&g_pool[cur * FH + tid], acc);
            acc = 0.f; cur = bb;
        }
        acc += outp[(size_t)n * FH + tid];
    }
    atomicAdd(&g_pool[cur * FH + tid], acc);
}

// ---------------- MLP tail ---------------------------------------------------
__global__ void mlp_kernel(const float* __restrict__ lw1, const float* __restrict__ lb1,
                           const float* __restrict__ lw2, const float* __restrict__ lb2,
                           float* __restrict__ out) {
    __shared__ float s_in[FH];
    __shared__ float s_mid[128];
    int g = blockIdx.x, tid = threadIdx.x;   // 128 threads
    float inv = 1.f / fmaxf((float)g_cnt[g], 1.f);
    s_in[tid]       = g_pool[g * FH + tid] * inv;
    s_in[tid + 128] = g_pool[g * FH + tid + 128] * inv;
    __syncthreads();
    float acc = lb1[tid];
    #pragma unroll 8
    for (int k = 0; k < FH; k++) acc = fmaf(s_in[k], lw1[k * 128 + tid], acc);
    s_mid[tid] = fmaxf(acc, 0.f);
    __syncthreads();
    if (tid < 10) {
        float a = lb2[tid];
        #pragma unroll 8
        for (int k = 0; k < 128; k++) a = fmaf(s_mid[k], lw2[k * 10 + tid], a);
        out[g * 10 + tid] = fmaxf(a, 0.f);
    }
}

// ---------------- launch ------------------------------------------------------
extern "C" void kernel_launch(void* const* d_in, const int* in_sizes, int n_in,
                              void* d_out, int out_size) {
    const float* x     = (const float*)d_in[0];
    const float* pos   = (const float*)d_in[1];
    const int*   ei    = (const int*)d_in[2];
    const int*   batch = (const int*)d_in[3];
    const float* W1   = (const float*)d_in[4];
    const float* as1  = (const float*)d_in[5];
    const float* ad1  = (const float*)d_in[6];
    const float* b1   = (const float*)d_in[7];
    const float* W2   = (const float*)d_in[8];
    const float* as2  = (const float*)d_in[9];
    const float* ad2  = (const float*)d_in[10];
    const float* b2   = (const float*)d_in[11];
    const float* lw1  = (const float*)d_in[12];
    const float* lb1  = (const float*)d_in[13];
    const float* lw2  = (const float*)d_in[14];
    const float* lb2  = (const float*)d_in[15];
    float* out = (float*)d_out;

    float *p_b1, *p_b2;
    cudaGetSymbolAddress((void**)&p_b1, g_buf1);
    cudaGetSymbolAddress((void**)&p_b2, g_buf2);

    // CSR build (by destination), self loops first
    init_deg_kernel<<<(NN + 255) / 256, 256>>>();
    hist_kernel<<<(EE + 255) / 256, 256>>>(ei);
    scan_kernel<<<1, 1024>>>();
    selfloop_kernel<<<(NN + 255) / 256, 256>>>();
    scatter_kernel<<<(EE + 255) / 256, 256>>>(ei);

    dim3 gg((NN + 127) / 128, HH);

    // ---- GAT layer 1 (concat fused into A-loader; alpha fused in epilogue) ----
    sgemm_fused<<<gg, 256>>>(nullptr, x, pos, W1, p_b1, 64, 1, as1, ad1);
    aggregate_kernel<<<NN, 128>>>(p_b1, b1, p_b2);

    // ---- GAT layer 2 ----
    sgemm_fused<<<gg, 256>>>(p_b2, x, pos, W2, p_b1, 256, 0, as2, ad2);
    aggregate_kernel<<<NN, 128>>>(p_b1, b2, p_b2);

    // ---- pool + MLP ----
    zero_pool_kernel<<<(BG * FH + 255) / 256, 256>>>();
    count_kernel<<<BG, 256>>>(batch);
    pool_kernel<<<(NN + 63) / 64, 256>>>(p_b2, batch);
    mlp_kernel<<<BG, 128>>>(lw1, lb1, lw2, lb2, out);
}

// round 4
// speedup vs baseline: 1.2881x; 1.1231x over previous
#include <cuda_runtime.h>
#include <math.h>

#define NN 20000
#define EE 320000
#define ET 340000   // EE + NN self loops
#define BG 32
#define FH 256      // H*C
#define HH 4
#define CC 64

typedef unsigned long long ull;

// ---------------- packed f32x2 helpers (FFMA2 — 2x fp32 FMA throughput) -----
__device__ __forceinline__ void fma2(ull &d, ull a, ull b) {
    asm("fma.rn.f32x2 %0, %1, %2, %0;" : "+l"(d) : "l"(a), "l"(b));
}
__device__ __forceinline__ ull add2(ull a, ull b) {
    ull r; asm("add.rn.f32x2 %0, %1, %2;" : "=l"(r) : "l"(a), "l"(b)); return r;
}
__device__ __forceinline__ ull dup2(float x) {
    ull r; asm("mov.b64 %0, {%1, %1};" : "=l"(r) : "f"(x)); return r;
}
__device__ __forceinline__ void unpack2(ull v, float &lo, float &hi) {
    asm("mov.b64 {%0, %1}, %2;" : "=f"(lo), "=f"(hi) : "l"(v));
}

// ---------------- scratch (device globals; no allocation allowed) ----------
__device__ __align__(16) float g_buf1[NN * FH];   // GEMM output (h)
__device__ __align__(16) float g_buf2[NN * FH];   // aggregation output
__device__ __align__(16) float g_as[NN * HH];
__device__ __align__(16) float g_ad[NN * HH];
__device__ __align__(16) int   g_deg[NN];
__device__ __align__(16) int   g_rowptr[NN + 1];
__device__ int   g_cursor[NN];
__device__ int   g_col[ET];
__device__ float g_pool[BG * FH];
__device__ int   g_cnt[BG];

// ---------------- init: deg=1 (self loop), zero pool/cnt --------------------
__global__ void init_zero_kernel() {
    int n = blockIdx.x * blockDim.x + threadIdx.x;
    if (n < NN) g_deg[n] = 1;
    if (n < BG * FH) g_pool[n] = 0.f;
    if (n < BG) g_cnt[n] = 0;
}

__global__ void hist_kernel(const int* __restrict__ ei) {
    int e = blockIdx.x * blockDim.x + threadIdx.x;
    if (e >= EE) return;
    int dst = ei[EE + e];
    atomicAdd(&g_deg[dst], 1);
}

// exclusive scan over g_deg + fused self-loop/cursor init, single block
__global__ void scan_selfloop_kernel() {
    __shared__ int wsum[32];
    int tid = threadIdx.x;
    int lane = tid & 31, wid = tid >> 5;
    int4 v[5];
    int sum = 0;
    if (tid < 1000) {               // 1000 * 20 = 20000 exactly
        const int4* p = (const int4*)(g_deg + tid * 20);
        #pragma unroll
        for (int i = 0; i < 5; i++) {
            v[i] = p[i];
            sum += v[i].x + v[i].y + v[i].z + v[i].w;
        }
    }
    int inc = sum;
    #pragma unroll
    for (int off = 1; off < 32; off <<= 1) {
        int u = __shfl_up_sync(0xffffffffu, inc, off);
        if (lane >= off) inc += u;
    }
    if (lane == 31) wsum[wid] = inc;
    __syncthreads();
    if (wid == 0) {
        int w = wsum[lane];
        #pragma unroll
        for (int off = 1; off < 32; off <<= 1) {
            int u = __shfl_up_sync(0xffffffffu, w, off);
            if (lane >= off) w += u;
        }
        wsum[lane] = w;
    }
    __syncthreads();
    int excl = inc - sum + (wid ? wsum[wid - 1] : 0);
    if (tid < 1000) {
        int run = excl;
        int base = tid * 20;
        int4* q = (int4*)(g_rowptr + base);
        #pragma unroll
        for (int i = 0; i < 5; i++) {
            int4 o;
            int n0 = base + i * 4;
            o.x = run; g_col[run] = n0;     g_cursor[n0]     = run + 1; run += v[i].x;
            o.y = run; g_col[run] = n0 + 1; g_cursor[n0 + 1] = run + 1; run += v[i].y;
            o.z = run; g_col[run] = n0 + 2; g_cursor[n0 + 2] = run + 1; run += v[i].z;
            o.w = run; g_col[run] = n0 + 3; g_cursor[n0 + 3] = run + 1; run += v[i].w;
            q[i] = o;
        }
    }
    if (tid == 0) g_rowptr[NN] = wsum[31];
}

__global__ void scatter_kernel(const int* __restrict__ ei) {
    int e = blockIdx.x * blockDim.x + threadIdx.x;
    if (e >= EE) return;
    int src = ei[e];
    int dst = ei[EE + e];
    int p = atomicAdd(&g_cursor[dst], 1);
    g_col[p] = src;
}

// ---------------- SGEMM (FFMA2) + fused concat(A) + fused alpha dots --------
__global__ void __launch_bounds__(256, 2)
sgemm_fused(const float* __restrict__ A, const float* __restrict__ x,
            const float* __restrict__ pos, const float* __restrict__ Bw,
            float* __restrict__ C, int K, int mode,
            const float* __restrict__ a_src, const float* __restrict__ a_dst) {
    __shared__ float As[16][132];   // [k][m], padded
    __shared__ float Bs[16][64];    // [k][n]
    __shared__ float s_as[64], s_ad[64];

    int tid = threadIdx.x;
    int bm = blockIdx.x * 128;
    int hd = blockIdx.y;            // head index (BN == CC)
    int bn = hd * 64;

    if (tid < 64) { s_as[tid] = a_src[bn + tid]; s_ad[tid] = a_dst[bn + tid]; }

    int ty = tid >> 4, tx = tid & 15;
    int m0 = ty * 8, n0 = tx * 4;
    int ar = tid >> 2;              // 0..63
    int ac = (tid & 3) * 4;         // 0,4,8,12
    int br = tid >> 4;              // 0..15
    int bc = (tid & 15) * 4;        // 0..60

    ull acc[4][4];
    #pragma unroll
    for (int i = 0; i < 4; i++)
        #pragma unroll
        for (int j = 0; j < 4; j++) acc[i][j] = 0ull;

    for (int k0 = 0; k0 < K; k0 += 16) {
        #pragma unroll
        for (int half = 0; half < 2; half++) {
            int r = ar + half * 64;
            int row = bm + r;
            float4 v = make_float4(0.f, 0.f, 0.f, 0.f);
            if (row < NN) {
                if (mode == 0) {
                    v = *(const float4*)(A + (size_t)row * K + k0 + ac);
                } else {
                    int c = k0 + ac;      // concat(pos[2], x[62])
                    if (c == 0) {
                        float2 p = *(const float2*)(pos + (size_t)row * 2);
                        float2 q = *(const float2*)(x + (size_t)row * 62);
                        v = make_float4(p.x, p.y, q.x, q.y);
                    } else {
                        float2 q0 = *(const float2*)(x + (size_t)row * 62 + c - 2);
                        float2 q1 = *(const float2*)(x + (size_t)row * 62 + c);
                        v = make_float4(q0.x, q0.y, q1.x, q1.y);
                    }
                }
            }
            As[ac + 0][r] = v.x; As[ac + 1][r] = v.y;
            As[ac + 2][r] = v.z; As[ac + 3][r] = v.w;
        }
        *(float4*)&Bs[br][bc] = *(const float4*)(Bw + (size_t)(k0 + br) * FH + bn + bc);
        __syncthreads();
        #pragma unroll
        for (int kk = 0; kk < 16; kk++) {
            float4 b4 = *(float4*)&Bs[kk][n0];
            ull bb0 = dup2(b4.x), bb1 = dup2(b4.y), bb2 = dup2(b4.z), bb3 = dup2(b4.w);
            ulonglong2 a01 = *(ulonglong2*)&As[kk][m0];
            ulonglong2 a23 = *(ulonglong2*)&As[kk][m0 + 4];
            ull aa[4] = {a01.x, a01.y, a23.x, a23.y};
            #pragma unroll
            for (int mi = 0; mi < 4; mi++) {
                fma2(acc[mi][0], aa[mi], bb0);
                fma2(acc[mi][1], aa[mi], bb1);
                fma2(acc[mi][2], aa[mi], bb2);
                fma2(acc[mi][3], aa[mi], bb3);
            }
        }
        __syncthreads();
    }

    // ---- fused alpha dots ----
    ull ps[4] = {0,0,0,0}, pd[4] = {0,0,0,0};
    #pragma unroll
    for (int nj = 0; nj < 4; nj++) {
        ull w_s = dup2(s_as[n0 + nj]);
        ull w_d = dup2(s_ad[n0 + nj]);
        #pragma unroll
        for (int mi = 0; mi < 4; mi++) {
            fma2(ps[mi], acc[mi][nj], w_s);
            fma2(pd[mi], acc[mi][nj], w_d);
        }
    }
    #pragma unroll
    for (int s = 1; s < 16; s <<= 1) {
        #pragma unroll
        for (int mi = 0; mi < 4; mi++) {
            ps[mi] = add2(ps[mi], __shfl_xor_sync(0xffffffffu, ps[mi], s));
            pd[mi] = add2(pd[mi], __shfl_xor_sync(0xffffffffu, pd[mi], s));
        }
    }
    if (tx == 0) {
        #pragma unroll
        for (int mi = 0; mi < 4; mi++) {
            int row = bm + m0 + 2 * mi;
            float slo, shi, dlo, dhi;
            unpack2(ps[mi], slo, shi);
            unpack2(pd[mi], dlo, dhi);
            if (row < NN)     { g_as[row * HH + hd] = slo; g_ad[row * HH + hd] = dlo; }
            if (row + 1 < NN) { g_as[(row + 1) * HH + hd] = shi; g_ad[(row + 1) * HH + hd] = dhi; }
        }
    }

    // ---- C writes ----
    #pragma unroll
    for (int mi = 0; mi < 4; mi++) {
        int row = bm + m0 + 2 * mi;
        float lo0, hi0, lo1, hi1, lo2, hi2, lo3, hi3;
        unpack2(acc[mi][0], lo0, hi0);
        unpack2(acc[mi][1], lo1, hi1);
        unpack2(acc[mi][2], lo2, hi2);
        unpack2(acc[mi][3], lo3, hi3);
        if (row < NN)
            *(float4*)(C + (size_t)row * FH + bn + n0) = make_float4(lo0, lo1, lo2, lo3);
        if (row + 1 < NN)
            *(float4*)(C + (size_t)(row + 1) * FH + bn + n0) = make_float4(hi0, hi1, hi2, hi3);
    }
}

// ---------------- attention aggregation: one block per dst node -------------
// warp 0: single-pass online softmax stats; all 128 threads: weighted gather
__global__ void aggregate_kernel(const float* __restrict__ h, const float* __restrict__ bias,
                                 float* __restrict__ outp) {
    int n = blockIdx.x;
    int tid = threadIdx.x;                  // 128
    int start = g_rowptr[n], end = g_rowptr[n + 1];

    __shared__ float s_m[HH];
    __shared__ float s_rd[HH];
    __shared__ float s_alpha[32][HH];
    __shared__ int   s_src[32];

    const float4* as4 = (const float4*)g_as;
    float4 adv = ((const float4*)g_ad)[n];
    float adh[HH] = {adv.x, adv.y, adv.z, adv.w};

    if (tid < 32) {
        // online softmax over this lane's edges
        float m[HH] = {-1e30f, -1e30f, -1e30f, -1e30f};
        float d[HH] = {0.f, 0.f, 0.f, 0.f};
        for (int j = start + tid; j < end; j += 32) {
            int s = g_col[j];
            float4 av = as4[s];
            float ee[HH] = {av.x + adh[0], av.y + adh[1], av.z + adh[2], av.w + adh[3]};
            #pragma unroll
            for (int hd = 0; hd < HH; hd++) {
                float e = ee[hd];
                e = (e > 0.f) ? e : 0.2f * e;
                float nm = fmaxf(m[hd], e);
                d[hd] = d[hd] * __expf(m[hd] - nm) + __expf(e - nm);
                m[hd] = nm;
            }
        }
        // warp combine of (m, d) pairs
        #pragma unroll
        for (int off = 16; off > 0; off >>= 1) {
            #pragma unroll
            for (int hd = 0; hd < HH; hd++) {
                float om = __shfl_xor_sync(0xffffffffu, m[hd], off);
                float od = __shfl_xor_sync(0xffffffffu, d[hd], off);
                float nm = fmaxf(m[hd], om);
                d[hd] = d[hd] * __expf(m[hd] - nm) + od * __expf(om - nm);
                m[hd] = nm;
            }
        }
        if (tid < HH) {
            s_m[tid] = m[tid];
            s_rd[tid] = 1.f / (d[tid] + 1e-16f);
        }
    }
    __syncthreads();

    // weighted gather-accumulate, 2 channels / thread
    float accA0 = 0.f, accA1 = 0.f, accB0 = 0.f, accB1 = 0.f;
    int c0 = 2 * tid;
    int myh = tid >> 5;         // head of channels 2*tid, 2*tid+1
    for (int base = start; base < end; base += 32) {
        int cnt = min(32, end - base);
        if (tid < cnt) {
            int s = g_col[base + tid];
            s_src[tid] = s;
            float4 av = as4[s];
            float ee[HH] = {av.x + adh[0], av.y + adh[1], av.z + adh[2], av.w + adh[3]};
            #pragma unroll
            for (int hd = 0; hd < HH; hd++) {
                float e = ee[hd];
                e = (e > 0.f) ? e : 0.2f * e;
                s_alpha[tid][hd] = __expf(e - s_m[hd]) * s_rd[hd];
            }
        }
        __syncthreads();
        int k = 0;
        for (; k + 2 <= cnt; k += 2) {
            int sA = s_src[k], sB = s_src[k + 1];
            float aA = s_alpha[k][myh], aB = s_alpha[k + 1][myh];
            float2 hA = *(const float2*)(h + (size_t)sA * FH + c0);
            float2 hB = *(const float2*)(h + (size_t)sB * FH + c0);
            accA0 = fmaf(hA.x, aA, accA0);
            accA1 = fmaf(hA.y, aA, accA1);
            accB0 = fmaf(hB.x, aB, accB0);
            accB1 = fmaf(hB.y, aB, accB1);
        }
        if (k < cnt) {
            int sA = s_src[k];
            float aA = s_alpha[k][myh];
            float2 hA = *(const float2*)(h + (size_t)sA * FH + c0);
            accA0 = fmaf(hA.x, aA, accA0);
            accA1 = fmaf(hA.y, aA, accA1);
        }
        __syncthreads();
    }
    outp[(size_t)n * FH + c0]     = accA0 + accB0 + bias[c0];
    outp[(size_t)n * FH + c0 + 1] = accA1 + accB1 + bias[c0 + 1];
}

// ---------------- pooling ---------------------------------------------------
__global__ void count_kernel(const int* __restrict__ batch) {
    __shared__ int s[256];
    int b = blockIdx.x, tid = threadIdx.x;
    int c = 0;
    for (int i = tid; i < NN; i += 256) c += (batch[i] == b);
    s[tid] = c;
    __syncthreads();
    for (int off = 128; off > 0; off >>= 1) {
        if (tid < off) s[tid] += s[tid + off];
        __syncthreads();
    }
    if (tid == 0) g_cnt[b] = s[0];
}

__global__ void pool_kernel(const float* __restrict__ outp, const int* __restrict__ batch) {
    int n0 = blockIdx.x * 64;
    int tid = threadIdx.x;                // 256 = channel
    int nend = min(n0 + 64, NN);
    float acc = 0.f;
    int cur = batch[n0];
    for (int n = n0; n < nend; n++) {
        int bb = batch[n];
        if (bb != cur) {
            atomicAdd(&g_pool[cur * FH + tid], acc);
            acc = 0.f; cur = bb;
        }
        acc += outp[(size_t)n * FH + tid];
    }
    atomicAdd(&g_pool[cur * FH + tid], acc);
}

// ---------------- MLP tail ---------------------------------------------------
__global__ void mlp_kernel(const float* __restrict__ lw1, const float* __restrict__ lb1,
                           const float* __restrict__ lw2, const float* __restrict__ lb2,
                           float* __restrict__ out) {
    __shared__ float s_in[FH];
    __shared__ float s_mid[128];
    int g = blockIdx.x, tid = threadIdx.x;   // 128 threads
    float inv = 1.f / fmaxf((float)g_cnt[g], 1.f);
    s_in[tid]       = g_pool[g * FH + tid] * inv;
    s_in[tid + 128] = g_pool[g * FH + tid + 128] * inv;
    __syncthreads();
    float acc = lb1[tid];
    #pragma unroll 8
    for (int k = 0; k < FH; k++) acc = fmaf(s_in[k], lw1[k * 128 + tid], acc);
    s_mid[tid] = fmaxf(acc, 0.f);
    __syncthreads();
    if (tid < 10) {
        float a = lb2[tid];
        #pragma unroll 8
        for (int k = 0; k < 128; k++) a = fmaf(s_mid[k], lw2[k * 10 + tid], a);
        out[g * 10 + tid] = fmaxf(a, 0.f);
    }
}

// ---------------- launch ------------------------------------------------------
extern "C" void kernel_launch(void* const* d_in, const int* in_sizes, int n_in,
                              void* d_out, int out_size) {
    const float* x     = (const float*)d_in[0];
    const float* pos   = (const float*)d_in[1];
    const int*   ei    = (const int*)d_in[2];
    const int*   batch = (const int*)d_in[3];
    const float* W1   = (const float*)d_in[4];
    const float* as1  = (const float*)d_in[5];
    const float* ad1  = (const float*)d_in[6];
    const float* b1   = (const float*)d_in[7];
    const float* W2   = (const float*)d_in[8];
    const float* as2  = (const float*)d_in[9];
    const float* ad2  = (const float*)d_in[10];
    const float* b2   = (const float*)d_in[11];
    const float* lw1  = (const float*)d_in[12];
    const float* lb1  = (const float*)d_in[13];
    const float* lw2  = (const float*)d_in[14];
    const float* lb2  = (const float*)d_in[15];
    float* out = (float*)d_out;

    float *p_b1, *p_b2;
    cudaGetSymbolAddress((void**)&p_b1, g_buf1);
    cudaGetSymbolAddress((void**)&p_b2, g_buf2);

    // side stream + events, created once OUTSIDE capture (first call is the
    // uncaptured correctness run). No work-dependent state: graph is identical
    // every call.
    static cudaStream_t s1 = nullptr;
    static cudaEvent_t ev_fork = nullptr, ev_join = nullptr;
    if (!s1) {
        cudaStreamCreateWithFlags(&s1, cudaStreamNonBlocking);
        cudaEventCreateWithFlags(&ev_fork, cudaEventDisableTiming);
        cudaEventCreateWithFlags(&ev_join, cudaEventDisableTiming);
    }

    dim3 gg((NN + 127) / 128, HH);

    // fork side stream off the main (capture) stream
    cudaEventRecord(ev_fork, 0);
    cudaStreamWaitEvent(s1, ev_fork, 0);

    // main stream: CSR build            side stream: GEMM1 + count
    init_zero_kernel<<<(NN + 255) / 256, 256>>>();
    hist_kernel<<<(EE + 255) / 256, 256>>>(ei);
    scan_selfloop_kernel<<<1, 1024>>>();
    sgemm_fused<<<gg, 256, 0, s1>>>(nullptr, x, pos, W1, p_b1, 64, 1, as1, ad1);
    scatter_kernel<<<(EE + 255) / 256, 256>>>(ei);
    count_kernel<<<BG, 256, 0, s1>>>(batch);

    // join
    cudaEventRecord(ev_join, s1);
    cudaStreamWaitEvent(0, ev_join, 0);

    // ---- GAT layer 1 aggregation ----
    aggregate_kernel<<<NN, 128>>>(p_b1, b1, p_b2);

    // ---- GAT layer 2 ----
    sgemm_fused<<<gg, 256>>>(p_b2, x, pos, W2, p_b1, 256, 0, as2, ad2);
    aggregate_kernel<<<NN, 128>>>(p_b1, b2, p_b2);

    // ---- pool + MLP ----
    pool_kernel<<<(NN + 63) / 64, 256>>>(p_b2, batch);
    mlp_kernel<<<BG, 128>>>(lw1, lb1, lw2, lb2, out);
}